// round 5
// baseline (speedup 1.0000x reference)
#include <cuda_runtime.h>
#include <stdint.h>
#include <math.h>

#define BATCH    256
#define NQ       1000
#define NC       81
#define NELEM    (NQ*NC)     /* 81000 */
#define KTOP     100
#define NT       1024
#define CANDBUF  2048
#define NITER_BS 24

__device__ __forceinline__ float sigm_precise(float x) { return 1.0f / (1.0f + expf(-x)); }
__device__ __forceinline__ float sigm_fast(float x)    { return __fdividef(1.0f, 1.0f + __expf(-x)); }

__global__ void __launch_bounds__(NT, 2)
postproc_kernel(const float* __restrict__ logits,   // [B,Q,C]
                const float* __restrict__ obj,      // [B,Q]
                const float* __restrict__ boxesIn,  // [B,Q,4]
                const float* __restrict__ unk,      // [B,Q]
                const float* __restrict__ tsz,      // [B,2]
                float* __restrict__ out)
{
    const int b   = blockIdx.x;
    const int tid = threadIdx.x;

    __shared__ float          fac[NQ];      // exp(-obj)*(1-sig(unk))  (PRECISE)
    __shared__ float          lastv[NQ];    // exp(-obj)*sig(unk)      (PRECISE)
    __shared__ unsigned       s_sum[NITER_BS];
    __shared__ unsigned       s_cnt, s_nq;
    __shared__ unsigned short qlist[NQ];    // surviving query ids
    __shared__ unsigned       cbits[CANDBUF];
    __shared__ unsigned       cidx[CANDBUF];

    // ---- per-query factors (precise; formula identical to verified kernel) ----
    for (int q = tid; q < NQ; q += NT) {
        float o  = obj[b * NQ + q];
        float uu = unk[b * NQ + q];
        float op = expf(-o);
        float su = sigm_precise(uu);
        fac[q]   = op * (1.0f - su);
        lastv[q] = op * su;
    }
    if (tid < NITER_BS) s_sum[tid] = 0;
    if (tid == 0) { s_cnt = 0; s_nq = 0; }
    __syncthreads();

    const float* L = logits + (size_t)b * NELEM;

    // ---- achieved samples: lastv[q] + fast probs of channels 0..3 (5 per query) ----
    float av0 = 0.f, av1 = 0.f, av2 = 0.f, av3 = 0.f, av4 = 0.f;
    if (tid < NQ) {
        float f = fac[tid];
        const float* Lq = L + (unsigned)tid * 81u;
        av0 = f * sigm_fast(Lq[0]);
        av1 = f * sigm_fast(Lq[1]);
        av2 = f * sigm_fast(Lq[2]);
        av3 = f * sigm_fast(Lq[3]);
        av4 = lastv[tid];
    }

    // ---- binary search: T1 = 100th-largest achieved approx value (5000 samples) ----
    unsigned lo = 0u, hi = 0x7F800001u;
    for (int it = 0; it < NITER_BS; ++it) {
        unsigned mid = lo + ((hi - lo) >> 1);
        unsigned cv = (unsigned)(__float_as_uint(av0) >= mid)
                    + (unsigned)(__float_as_uint(av1) >= mid)
                    + (unsigned)(__float_as_uint(av2) >= mid)
                    + (unsigned)(__float_as_uint(av3) >= mid)
                    + (unsigned)(__float_as_uint(av4) >= mid);
        unsigned cw = __reduce_add_sync(0xFFFFFFFFu, cv);
        if ((tid & 31) == 0) atomicAdd(&s_sum[it], cw);
        __syncthreads();
        if (s_sum[it] >= KTOP) lo = mid; else hi = mid;
    }
    const float    T1f    = __uint_as_float(lo);
    const unsigned T_keep = __float_as_uint(T1f * 0.99998f);  // element keep (margin >> approx err)
    const float    Tq     = T1f * 0.99997f;                   // query prune (extra margin)

    // ---- lastv candidates + survivor-query compaction (no logit loads yet) ----
    if (tid < NQ) {
        if (__float_as_uint(lastv[tid]) >= T_keep) {
            unsigned p = atomicAdd(&s_cnt, 1u);
            if (p < CANDBUF) cidx[p] = (unsigned)tid * 81u + 80u;
        }
        if (fac[tid] >= Tq) {                    // fac < Tq  =>  all 60 sigm channels provably out
            unsigned p = atomicAdd(&s_nq, 1u);
            qlist[p] = (unsigned short)tid;
        }
    }
    __syncthreads();
    const unsigned nq = s_nq;

    // ---- scan ONLY surviving queries: half-warp (16 lanes) per query ----
    // lane j reads channels {j, j+16, j+32, j+48} (<60): 64B-contiguous per step.
    {
        const unsigned j = tid & 15u;
        for (unsigned s = (unsigned)tid >> 4; s < nq; s += NT / 16) {
            unsigned q = qlist[s];
            float f = fac[q];
            const float* Lq = L + q * 81u;
            #pragma unroll
            for (int k = 0; k < 4; ++k) {
                unsigned c = j + 16u * (unsigned)k;
                if (c < 60u) {
                    float p = f * sigm_fast(Lq[c]);
                    if (__float_as_uint(p) >= T_keep) {
                        unsigned pos = atomicAdd(&s_cnt, 1u);
                        if (pos < CANDBUF) cidx[pos] = q * 81u + c;
                    }
                }
            }
        }
    }
    __syncthreads();
    const unsigned nF = (s_cnt < CANDBUF) ? s_cnt : CANDBUF;

    // ---- recompute candidates PRECISELY (bit-identical to verified formula) ----
    for (unsigned i = tid; i < nF; i += NT) {
        unsigned e = cidx[i];
        unsigned q = e / 81u;
        unsigned c = e - q * 81u;
        float p = (c < 60u) ? fac[q] * sigm_precise(L[e]) : lastv[q];
        cbits[i] = __float_as_uint(p);
    }
    __syncthreads();

    // ---- exact rank ordering (precise value desc, index asc) and output ----
    const float* Bx = boxesIn + (size_t)b * NQ * 4;
    const float ih = tsz[b * 2 + 0];
    const float iw = tsz[b * 2 + 1];

    for (unsigned i = tid; i < nF; i += NT) {
        unsigned bi = cbits[i], xi = cidx[i];
        unsigned r = 0;
        for (unsigned jj = 0; jj < nF; jj++) {
            unsigned bj = cbits[jj], xj = cidx[jj];
            r += (bj > bi) || (bj == bi && xj < xi);
        }
        if (r < KTOP) {
            unsigned q = xi / 81u;
            unsigned c = xi - q * 81u;
            out[(size_t)b * KTOP + r]                        = __uint_as_float(bi);
            out[(size_t)BATCH * KTOP + (size_t)b * KTOP + r] = (float)c;
            float cx = Bx[q * 4 + 0], cy = Bx[q * 4 + 1];
            float ww = Bx[q * 4 + 2], hh = Bx[q * 4 + 3];
            float* ob = out + (size_t)2 * BATCH * KTOP + ((size_t)b * KTOP + r) * 4;
            ob[0] = (cx - 0.5f * ww) * iw;
            ob[1] = (cy - 0.5f * hh) * ih;
            ob[2] = (cx + 0.5f * ww) * iw;
            ob[3] = (cy + 0.5f * hh) * ih;
        }
    }
}

extern "C" void kernel_launch(void* const* d_in, const int* in_sizes, int n_in,
                              void* d_out, int out_size)
{
    const float* logits  = (const float*)d_in[0];  // (256,1000,81)
    const float* obj     = (const float*)d_in[1];  // (256,1000)
    const float* boxesIn = (const float*)d_in[2];  // (256,1000,4)
    const float* unk     = (const float*)d_in[3];  // (256,1000)
    const float* tsz     = (const float*)d_in[4];  // (256,2)
    float* out = (float*)d_out;
    (void)in_sizes; (void)n_in; (void)out_size;

    postproc_kernel<<<BATCH, NT>>>(logits, obj, boxesIn, unk, tsz, out);
}

// round 6
// speedup vs baseline: 3.8723x; 3.8723x over previous
#include <cuda_runtime.h>
#include <stdint.h>
#include <math.h>

#define BATCH    256
#define NQ       1000
#define NC       81
#define NELEM    (NQ*NC)     /* 81000 */
#define KTOP     100
#define NT       512
#define CANDBUF  1024
#define TF_ITERS 18
#define BS_ITERS 26

__device__ __forceinline__ float sigm_precise(float x) { return 1.0f / (1.0f + expf(-x)); }
__device__ __forceinline__ float sigm_fast(float x)    { return __fdividef(1.0f, 1.0f + __expf(-x)); }

__global__ void __launch_bounds__(NT, 2)
postproc_kernel(const float* __restrict__ logits,   // [B,Q,C]
                const float* __restrict__ obj,      // [B,Q]
                const float* __restrict__ boxesIn,  // [B,Q,4]
                const float* __restrict__ unk,      // [B,Q]
                const float* __restrict__ tsz,      // [B,2]
                float* __restrict__ out)
{
    const int b   = blockIdx.x;
    const int tid = threadIdx.x;

    __shared__ float          fac[NQ];      // exp(-obj)*(1-sig(unk))  (PRECISE)
    __shared__ float          lastv[NQ];    // exp(-obj)*sig(unk)      (PRECISE)
    __shared__ unsigned short qlist[NQ];
    __shared__ unsigned       s_sum[TF_ITERS + BS_ITERS];
    __shared__ unsigned       s_cnt, s_nq;
    __shared__ unsigned       cbits[CANDBUF];
    __shared__ unsigned       cidx[CANDBUF];

    // ---- per-query factors (precise; identical formula to verified kernel) ----
    for (int q = tid; q < NQ; q += NT) {
        float o  = obj[b * NQ + q];
        float uu = unk[b * NQ + q];
        float op = expf(-o);
        float su = sigm_precise(uu);
        fac[q]   = op * (1.0f - su);
        lastv[q] = op * su;
    }
    if (tid < TF_ITERS + BS_ITERS) s_sum[tid] = 0;
    if (tid == 0) { s_cnt = 0; s_nq = 0; }
    __syncthreads();

    const float* L = logits + (size_t)b * NELEM;

    // ---- probe: per-query achieved sample = max(fac*sig(max logit c0..7), lastv) ----
    float smp0 = 0.f, smp1 = 0.f;
    if (tid < NQ) {
        const float* Lq = L + (unsigned)tid * 81u;
        float m = Lq[0];
        #pragma unroll
        for (int c = 1; c < 8; ++c) m = fmaxf(m, Lq[c]);
        smp0 = fmaxf(fac[tid] * sigm_fast(m), lastv[tid]);
    }
    if (tid + NT < NQ) {
        unsigned q = (unsigned)tid + NT;
        const float* Lq = L + q * 81u;
        float m = Lq[0];
        #pragma unroll
        for (int c = 1; c < 8; ++c) m = fmaxf(m, Lq[c]);
        smp1 = fmaxf(fac[q] * sigm_fast(m), lastv[q]);
    }

    // ---- floor BS: Tf = ~100th-largest achieved sample (valid floor <= P100) ----
    unsigned lo = 0u, hi = 0x7F800001u;
    for (int it = 0; it < TF_ITERS; ++it) {
        unsigned mid = lo + ((hi - lo) >> 1);
        unsigned cv = (unsigned)(__float_as_uint(smp0) >= mid)
                    + (unsigned)(__float_as_uint(smp1) >= mid);
        unsigned cw = __reduce_add_sync(0xFFFFFFFFu, cv);
        if ((tid & 31) == 0) atomicAdd(&s_sum[it], cw);
        __syncthreads();
        if (s_sum[it] >= KTOP) lo = mid; else hi = mid;
    }
    const float Tq = __uint_as_float(lo) * 0.99997f;   // query-prune threshold (margin >> approx err)

    // ---- survivor-query compaction (pruned queries: 60 logits NEVER loaded) ----
    for (int q = tid; q < NQ; q += NT) {
        if (fac[q] >= Tq) {
            unsigned p = atomicAdd(&s_nq, 1u);
            qlist[p] = (unsigned short)q;
        }
    }
    __syncthreads();
    const unsigned nq = s_nq;

    // ---- scan survivors: half-warp (16 lanes) per query, per-lane top-4 ----
    unsigned b0 = 0, b1 = 0, b2 = 0, b3 = 0;
    unsigned i0 = 0xFFFFFFFFu, i1 = 0xFFFFFFFFu, i2 = 0xFFFFFFFFu, i3 = 0xFFFFFFFFu;
    const unsigned hw = (unsigned)tid >> 4, j = (unsigned)tid & 15u;

    for (unsigned s = hw; s < nq; s += NT / 16) {
        unsigned q = qlist[s];
        float f = fac[q];
        const float* Lq = L + q * 81u;
        #pragma unroll
        for (int k = 0; k < 4; ++k) {
            unsigned c = j + 16u * (unsigned)k;
            if (c < 60u) {
                float p = f * sigm_fast(Lq[c]);
                unsigned pb = __float_as_uint(p);
                if (pb > b3) {
                    unsigned ee = q * 81u + c;
                    if (pb > b1) {
                        if (pb > b0) { b3=b2;i3=i2; b2=b1;i2=i1; b1=b0;i1=i0; b0=pb;i0=ee; }
                        else         { b3=b2;i3=i2; b2=b1;i2=i1; b1=pb;i1=ee; }
                    } else {
                        if (pb > b2) { b3=b2;i3=i2; b2=pb;i2=ee; }
                        else         { b3=pb;i3=ee; }
                    }
                }
            }
        }
    }
    __syncthreads();

    // ---- main BS over kept top-4s + ALL lastv values: tight T_keep (nF ~ 110) ----
    unsigned lb0 = (tid < NQ)      ? __float_as_uint(lastv[tid])      : 0u;
    unsigned lb1 = (tid + NT < NQ) ? __float_as_uint(lastv[tid + NT]) : 0u;
    lo = 0u; hi = 0x7F800001u;
    for (int it = 0; it < BS_ITERS; ++it) {
        unsigned mid = lo + ((hi - lo) >> 1);
        unsigned cv = (unsigned)(b0 >= mid) + (unsigned)(b1 >= mid)
                    + (unsigned)(b2 >= mid) + (unsigned)(b3 >= mid)
                    + (unsigned)(lb0 >= mid) + (unsigned)(lb1 >= mid);
        unsigned cw = __reduce_add_sync(0xFFFFFFFFu, cv);
        if ((tid & 31) == 0) atomicAdd(&s_sum[TF_ITERS + it], cw);
        __syncthreads();
        if (s_sum[TF_ITERS + it] >= KTOP) lo = mid; else hi = mid;
    }
    unsigned T_keep = 0u;
    if (lo != 0u) T_keep = __float_as_uint(__uint_as_float(lo) * 0.99998f);

    // ---- collect candidates (approx >= T_keep): provable superset of top-100 ----
    if (b0 >= T_keep && i0 != 0xFFFFFFFFu) { unsigned p = atomicAdd(&s_cnt, 1u); if (p < CANDBUF) cidx[p] = i0; }
    if (b1 >= T_keep && i1 != 0xFFFFFFFFu) { unsigned p = atomicAdd(&s_cnt, 1u); if (p < CANDBUF) cidx[p] = i1; }
    if (b2 >= T_keep && i2 != 0xFFFFFFFFu) { unsigned p = atomicAdd(&s_cnt, 1u); if (p < CANDBUF) cidx[p] = i2; }
    if (b3 >= T_keep && i3 != 0xFFFFFFFFu) { unsigned p = atomicAdd(&s_cnt, 1u); if (p < CANDBUF) cidx[p] = i3; }
    if (lb0 >= T_keep && tid < NQ) {
        unsigned p = atomicAdd(&s_cnt, 1u); if (p < CANDBUF) cidx[p] = (unsigned)tid * 81u + 80u;
    }
    if (lb1 >= T_keep && tid + NT < NQ) {
        unsigned p = atomicAdd(&s_cnt, 1u); if (p < CANDBUF) cidx[p] = ((unsigned)tid + NT) * 81u + 80u;
    }

    if (b3 >= T_keep) {
        // this lane may have dropped qualifiers: rescan ONLY its own queries (L1/L2-hot)
        for (unsigned s = hw; s < nq; s += NT / 16) {
            unsigned q = qlist[s];
            float f = fac[q];
            const float* Lq = L + q * 81u;
            #pragma unroll
            for (int k = 0; k < 4; ++k) {
                unsigned c = j + 16u * (unsigned)k;
                if (c < 60u) {
                    float p = f * sigm_fast(Lq[c]);
                    unsigned pb = __float_as_uint(p);
                    unsigned ee = q * 81u + c;
                    if (pb >= T_keep && ee != i0 && ee != i1 && ee != i2 && ee != i3) {
                        unsigned pos = atomicAdd(&s_cnt, 1u);
                        if (pos < CANDBUF) cidx[pos] = ee;
                    }
                }
            }
        }
    }
    __syncthreads();
    const unsigned nF = (s_cnt < CANDBUF) ? s_cnt : CANDBUF;

    // ---- recompute candidates PRECISELY (bit-identical to verified formula) ----
    for (unsigned i = tid; i < nF; i += NT) {
        unsigned e = cidx[i];
        unsigned q = e / 81u;
        unsigned c = e - q * 81u;
        float p = (c < 60u) ? fac[q] * sigm_precise(L[e]) : lastv[q];
        cbits[i] = __float_as_uint(p);
    }
    __syncthreads();

    // ---- exact rank ordering (precise value desc, index asc) and output ----
    const float* Bx = boxesIn + (size_t)b * NQ * 4;
    const float ih = tsz[b * 2 + 0];
    const float iw = tsz[b * 2 + 1];

    for (unsigned i = tid; i < nF; i += NT) {
        unsigned bi = cbits[i], xi = cidx[i];
        unsigned r = 0;
        for (unsigned jj = 0; jj < nF; jj++) {
            unsigned bj = cbits[jj], xj = cidx[jj];
            r += (bj > bi) || (bj == bi && xj < xi);
        }
        if (r < KTOP) {
            unsigned q = xi / 81u;
            unsigned c = xi - q * 81u;
            out[(size_t)b * KTOP + r]                        = __uint_as_float(bi);
            out[(size_t)BATCH * KTOP + (size_t)b * KTOP + r] = (float)c;
            float cx = Bx[q * 4 + 0], cy = Bx[q * 4 + 1];
            float ww = Bx[q * 4 + 2], hh = Bx[q * 4 + 3];
            float* ob = out + (size_t)2 * BATCH * KTOP + ((size_t)b * KTOP + r) * 4;
            ob[0] = (cx - 0.5f * ww) * iw;
            ob[1] = (cy - 0.5f * hh) * ih;
            ob[2] = (cx + 0.5f * ww) * iw;
            ob[3] = (cy + 0.5f * hh) * ih;
        }
    }
}

extern "C" void kernel_launch(void* const* d_in, const int* in_sizes, int n_in,
                              void* d_out, int out_size)
{
    const float* logits  = (const float*)d_in[0];  // (256,1000,81)
    const float* obj     = (const float*)d_in[1];  // (256,1000)
    const float* boxesIn = (const float*)d_in[2];  // (256,1000,4)
    const float* unk     = (const float*)d_in[3];  // (256,1000)
    const float* tsz     = (const float*)d_in[4];  // (256,2)
    float* out = (float*)d_out;
    (void)in_sizes; (void)n_in; (void)out_size;

    postproc_kernel<<<BATCH, NT>>>(logits, obj, boxesIn, unk, tsz, out);
}